// round 4
// baseline (speedup 1.0000x reference)
#include <cuda_runtime.h>
#include <cstdint>

#define N 4096
#define D 128

// ---------------- device globals (scratch; no allocations allowed) ----------------
__device__ __align__(16) float g_en[N * D];   // normalized embeddings
__device__ float g_tsorted[N];                // sorted targets
__device__ unsigned g_vloBits, g_vhiBits;     // selected order-statistic bit patterns
__device__ float    g_frac;                   // interpolation fraction (fp32, jax-exact)
__device__ unsigned char g_low[N];
__device__ unsigned g_rowMinPos[N];  // encoded min-dot over positive mask (per anchor)
__device__ unsigned g_rowMaxNeg[N];  // encoded max-dot over negative mask (per anchor)

// order-preserving float <-> uint encode
__device__ __forceinline__ unsigned encodeF(float f) {
    unsigned u = __float_as_uint(f);
    return (u & 0x80000000u) ? ~u : (u | 0x80000000u);
}
__device__ __forceinline__ float decodeF(unsigned u) {
    return (u & 0x80000000u) ? __uint_as_float(u & 0x7FFFFFFFu)
                             : __uint_as_float(~u);
}

// bitonic sort of s[N] in shared memory, 1024 threads
__device__ void bitonicSort(float* s) {
    int tid = threadIdx.x;
    for (int k = 2; k <= N; k <<= 1) {
        for (int j = k >> 1; j > 0; j >>= 1) {
            for (int idx = tid; idx < N; idx += 1024) {
                int p = idx ^ j;
                if (p > idx) {
                    float a = s[idx], b = s[p];
                    bool up = ((idx & k) == 0);
                    bool sw = up ? (a > b) : (a < b);
                    if (sw) { s[idx] = b; s[p] = a; }
                }
            }
            __syncthreads();
        }
    }
}

// ---------------- K1: fused init + normalize + sorts ----------------
__global__ void prepK(const float* __restrict__ emb, const float* __restrict__ au,
                      const float* __restrict__ tg) {
    __shared__ float s[N];
    __shared__ float thSh;
    int tid = threadIdx.x;  // 1024
    if (blockIdx.x < 128) {
        int row = blockIdx.x * 32 + (tid >> 5);
        int lane = tid & 31;
        const float4* p = (const float4*)(emb + (size_t)row * D);
        float4 v = p[lane];
        float ss = v.x * v.x + v.y * v.y + v.z * v.z + v.w * v.w;
#pragma unroll
        for (int st = 16; st > 0; st >>= 1) ss += __shfl_xor_sync(0xffffffffu, ss, st);
        float inv = 1.0f / fmaxf(sqrtf(ss), 1e-12f);
        float4 o;
        o.x = v.x * inv; o.y = v.y * inv; o.z = v.z * inv; o.w = v.w * inv;
        ((float4*)(g_en + (size_t)row * D))[lane] = o;
        return;
    }
    if (blockIdx.x == 128) {
        // init accumulators + sort aleatoric uncertainty -> median -> low mask
        for (int x = tid; x < N; x += 1024) {
            g_rowMinPos[x] = 0xFFFFFFFFu;
            g_rowMaxNeg[x] = 0u;
        }
        for (int i = tid; i < N; i += 1024) s[i] = au[i];
        __syncthreads();
        bitonicSort(s);
        if (tid == 0) thSh = 0.5f * s[2047] + 0.5f * s[2048];
        __syncthreads();
        float th = thSh;
        for (int i = tid; i < N; i += 1024) g_low[i] = (au[i] < th) ? 1 : 0;
        return;
    }
    // block 129: sort targets
    for (int i = tid; i < N; i += 1024) s[i] = tg[i];
    __syncthreads();
    bitonicSort(s);
    for (int i = tid; i < N; i += 1024) g_tsorted[i] = s[i];
}

// block-wide reduce-sum of unsigned with broadcast to all threads
__device__ unsigned blockSumBcast(unsigned v, unsigned* warpS) {
    int tid = threadIdx.x, lane = tid & 31, wid = tid >> 5;
#pragma unroll
    for (int s = 16; s > 0; s >>= 1) v += __shfl_xor_sync(0xffffffffu, v, s);
    __syncthreads();
    if (lane == 0) warpS[wid] = v;
    __syncthreads();
    if (wid == 0) {
        unsigned w = warpS[lane];
#pragma unroll
        for (int s = 16; s > 0; s >>= 1) w += __shfl_xor_sync(0xffffffffu, w, s);
        if (lane == 0) warpS[0] = w;
    }
    __syncthreads();
    unsigned r = warpS[0];
    __syncthreads();
    return r;
}

// count pairs (i<j in sorted order) with fl(ts[j] - ts[i]) <= x   (x >= 0)
// 4 interleaved independent binary searches per thread to hide LDS latency
__device__ unsigned cntLE(const float* ts, float x, unsigned* warpS) {
    int tid = threadIdx.x;
    int i0 = tid, i1 = tid + 1024, i2 = tid + 2048, i3 = tid + 3072;
    float t0 = ts[i0], t1 = ts[i1], t2 = ts[i2], t3 = ts[i3];
    int lo0 = i0, hi0 = N - 1;
    int lo1 = i1, hi1 = N - 1;
    int lo2 = i2, hi2 = N - 1;
    int lo3 = i3, hi3 = N - 1;
#pragma unroll 1
    for (int s = 0; s < 12; s++) {
        if (lo0 < hi0) { int m = (lo0 + hi0 + 1) >> 1; if (ts[m] - t0 <= x) lo0 = m; else hi0 = m - 1; }
        if (lo1 < hi1) { int m = (lo1 + hi1 + 1) >> 1; if (ts[m] - t1 <= x) lo1 = m; else hi1 = m - 1; }
        if (lo2 < hi2) { int m = (lo2 + hi2 + 1) >> 1; if (ts[m] - t2 <= x) lo2 = m; else hi2 = m - 1; }
        if (lo3 < hi3) { int m = (lo3 + hi3 + 1) >> 1; if (ts[m] - t3 <= x) lo3 = m; else hi3 = m - 1; }
    }
    unsigned c = (unsigned)((lo0 - i0) + (lo1 - i1) + (lo2 - i2) + (lo3 - i3));
    return blockSumBcast(c, warpS);
}

// ---------------- K2: exact quantile order statistics via bit-pattern binary search ----------------
__global__ void selectK() {
    __shared__ float ts[N];
    __shared__ unsigned warpS[32];
    int tid = threadIdx.x;  // 1024
    for (int i = tid; i < N; i += 1024) ts[i] = g_tsorted[i];
    __syncthreads();

    // zero pairs (diff == 0)
    unsigned z = cntLE(ts, 0.0f, warpS);

    // replicate jax fp32 rank arithmetic
    unsigned long long n = 16773120ull - 2ull * (unsigned long long)z;
    float nf = (float)(n - 1ull);
    float pos = 0.2f * nf;
    float lof = floorf(pos);
    float frac = pos - lof;
    unsigned flatLo = (unsigned)lof;
    unsigned flatHi = (frac > 0.0f) ? flatLo + 1u : flatLo;
    // flat (duplicated) rank -> unordered-pair rank
    unsigned k = (blockIdx.x == 0) ? (flatLo >> 1) : (flatHi >> 1);
    unsigned target = k + 1u + z;   // want minimal v with cntLE(v) >= target

    unsigned lov = 0u, hiv = 0x7F7FFFFFu;
#pragma unroll 1
    while (lov < hiv) {
        unsigned mid = (lov + hiv) >> 1;
        unsigned c = cntLE(ts, __uint_as_float(mid), warpS);
        if (c >= target) hiv = mid; else lov = mid + 1u;
    }
    if (tid == 0) {
        if (blockIdx.x == 0) { g_vloBits = hiv; g_frac = frac; }
        else g_vhiBits = hiv;
    }
}

// ---------------- K3: symmetric scalar-FFMA GEMM + fused masked row/col reductions ----------------
__global__ __launch_bounds__(256, 2) void gemmMaskK(const float* __restrict__ t) {
    __shared__ __align__(16) float As[32][136];
    __shared__ __align__(16) float Bs[32][136];
    __shared__ unsigned sColMin[8][128];
    __shared__ unsigned sColMax[8][128];

    int tid = threadIdx.x;
    // triangular block mapping: bi <= bj over 32x32 tiles (528 blocks)
    int b = blockIdx.x;
    int bi = 0;
    while (b >= 32 - bi) { b -= 32 - bi; bi++; }
    int bj = bi + b;
    int ri = bi * 128, rj = bj * 128;

    int r0 = (tid >> 4) * 4;
    int c0 = (tid & 15) * 4;

    float acc[8][8];
#pragma unroll
    for (int r = 0; r < 8; r++)
#pragma unroll
        for (int c = 0; c < 8; c++) acc[r][c] = 0.0f;

    int lr = tid >> 1, lh = tid & 1;
    for (int kc = 0; kc < 4; kc++) {
        const float4* pa = (const float4*)(g_en + (size_t)(ri + lr) * D + kc * 32 + lh * 16);
        const float4* pb = (const float4*)(g_en + (size_t)(rj + lr) * D + kc * 32 + lh * 16);
        float4 a0 = pa[0], a1 = pa[1], a2 = pa[2], a3 = pa[3];
        float4 b0 = pb[0], b1 = pb[1], b2 = pb[2], b3 = pb[3];
        if (kc) __syncthreads();
        int kb = lh * 16;
        As[kb + 0][lr] = a0.x; As[kb + 1][lr] = a0.y; As[kb + 2][lr] = a0.z; As[kb + 3][lr] = a0.w;
        As[kb + 4][lr] = a1.x; As[kb + 5][lr] = a1.y; As[kb + 6][lr] = a1.z; As[kb + 7][lr] = a1.w;
        As[kb + 8][lr] = a2.x; As[kb + 9][lr] = a2.y; As[kb + 10][lr] = a2.z; As[kb + 11][lr] = a2.w;
        As[kb + 12][lr] = a3.x; As[kb + 13][lr] = a3.y; As[kb + 14][lr] = a3.z; As[kb + 15][lr] = a3.w;
        Bs[kb + 0][lr] = b0.x; Bs[kb + 1][lr] = b0.y; Bs[kb + 2][lr] = b0.z; Bs[kb + 3][lr] = b0.w;
        Bs[kb + 4][lr] = b1.x; Bs[kb + 5][lr] = b1.y; Bs[kb + 6][lr] = b1.z; Bs[kb + 7][lr] = b1.w;
        Bs[kb + 8][lr] = b2.x; Bs[kb + 9][lr] = b2.y; Bs[kb + 10][lr] = b2.z; Bs[kb + 11][lr] = b2.w;
        Bs[kb + 12][lr] = b3.x; Bs[kb + 13][lr] = b3.y; Bs[kb + 14][lr] = b3.z; Bs[kb + 15][lr] = b3.w;
        __syncthreads();
#pragma unroll 8
        for (int k = 0; k < 32; k++) {
            float4 x0 = *(const float4*)&As[k][r0];
            float4 x1 = *(const float4*)&As[k][64 + r0];
            float4 y0 = *(const float4*)&Bs[k][c0];
            float4 y1 = *(const float4*)&Bs[k][64 + c0];
            float a[8] = {x0.x, x0.y, x0.z, x0.w, x1.x, x1.y, x1.z, x1.w};
            float bb[8] = {y0.x, y0.y, y0.z, y0.w, y1.x, y1.y, y1.z, y1.w};
#pragma unroll
            for (int r = 0; r < 8; r++)
#pragma unroll
                for (int c = 0; c < 8; c++) acc[r][c] += a[r] * bb[c];
        }
    }

    // act threshold (computed inline; deterministic)
    float flo = __uint_as_float(g_vloBits);
    float fhi = __uint_as_float(g_vhiBits);
    float fr = g_frac;
    float actT = __fadd_rn(__fmul_rn(flo, 1.0f - fr), __fmul_rn(fhi, fr));

    // ---- fused epilogue: masked min/max for BOTH row anchors and col anchors ----
    int rows[8], cols[8];
#pragma unroll
    for (int u = 0; u < 4; u++) {
        rows[u] = ri + r0 + u;
        rows[4 + u] = ri + 64 + r0 + u;
        cols[u] = rj + c0 + u;
        cols[4 + u] = rj + 64 + c0 + u;
    }
    float ti[8], tj[8];
    int li[8], lj[8];
#pragma unroll
    for (int u = 0; u < 8; u++) {
        ti[u] = t[rows[u]];
        tj[u] = t[cols[u]];
        li[u] = g_low[rows[u]];
        lj[u] = g_low[cols[u]];
    }
    float pMin[8], nMax[8], cMin[8], cMax[8];
#pragma unroll
    for (int u = 0; u < 8; u++) {
        pMin[u] = 3.402823466e38f; nMax[u] = -3.402823466e38f;
        cMin[u] = 3.402823466e38f; cMax[u] = -3.402823466e38f;
    }
#pragma unroll
    for (int r = 0; r < 8; r++) {
#pragma unroll
        for (int c = 0; c < 8; c++) {
            float ad = fabsf(ti[r] - tj[c]);
            if (ad < actT) {
                float dv = acc[r][c];
                bool neq = rows[r] != cols[c];
                if (lj[c]) { if (neq) pMin[r] = fminf(pMin[r], dv); }
                else nMax[r] = fmaxf(nMax[r], dv);
                if (li[r]) { if (neq) cMin[c] = fminf(cMin[c], dv); }
                else cMax[c] = fmaxf(cMax[c], dv);
            }
        }
    }
    // row side: reduce across 16-lane groups sharing the same rows
#pragma unroll
    for (int s = 8; s > 0; s >>= 1) {
#pragma unroll
        for (int r = 0; r < 8; r++) {
            pMin[r] = fminf(pMin[r], __shfl_down_sync(0xffffffffu, pMin[r], s, 16));
            nMax[r] = fmaxf(nMax[r], __shfl_down_sync(0xffffffffu, nMax[r], s, 16));
        }
    }
    if ((tid & 15) == 0) {
#pragma unroll
        for (int r = 0; r < 8; r++) {
            if (pMin[r] < 3.0e38f) atomicMin(&g_rowMinPos[rows[r]], encodeF(pMin[r]));
            if (nMax[r] > -3.0e38f) atomicMax(&g_rowMaxNeg[rows[r]], encodeF(nMax[r]));
        }
    }
    // col side: combine lane pairs (l, l^16), stage per-warp partials, then flush
    unsigned eMin[8], eMax[8];
#pragma unroll
    for (int u = 0; u < 8; u++) {
        eMin[u] = encodeF(cMin[u]);
        eMax[u] = encodeF(cMax[u]);
        eMin[u] = min(eMin[u], __shfl_xor_sync(0xffffffffu, eMin[u], 16));
        eMax[u] = max(eMax[u], __shfl_xor_sync(0xffffffffu, eMax[u], 16));
    }
    int wrp = tid >> 5;
    if ((tid & 31) < 16) {
#pragma unroll
        for (int u = 0; u < 4; u++) {
            sColMin[wrp][c0 + u] = eMin[u];
            sColMin[wrp][64 + c0 + u] = eMin[4 + u];
            sColMax[wrp][c0 + u] = eMax[u];
            sColMax[wrp][64 + c0 + u] = eMax[4 + u];
        }
    }
    __syncthreads();
    if (tid < 128) {
        unsigned v = sColMin[0][tid];
#pragma unroll
        for (int w = 1; w < 8; w++) v = min(v, sColMin[w][tid]);
        if (v < 0xFF000000u) atomicMin(&g_rowMinPos[rj + tid], v);
    } else if (tid < 256) {
        int c = tid - 128;
        unsigned v = sColMax[0][c];
#pragma unroll
        for (int w = 1; w < 8; w++) v = max(v, sColMax[w][c]);
        if (v > 0x01000000u) atomicMax(&g_rowMaxNeg[rj + c], v);
    }
}

// ---------------- K4: per-anchor loss + mean ----------------
__global__ void finalK(float* __restrict__ out, int out_size) {
    __shared__ float sSum[32];
    __shared__ unsigned sCnt[32];
    int tid = threadIdx.x;  // 1024
    int lane = tid & 31, wid = tid >> 5;
    float sum = 0.0f;
    unsigned cnt = 0u;
    for (int i = tid; i < N; i += 1024) {
        if (!g_low[i]) continue;
        unsigned ep = g_rowMinPos[i];
        if (ep == 0xFFFFFFFFu) continue;  // no positive
        unsigned en = g_rowMaxNeg[i];
        if (en == 0u) continue;           // no negative
        float minDot = decodeF(ep);
        float maxDot = decodeF(en);
        float hp = sqrtf(fmaxf(2.0f - 2.0f * minDot, 1e-12f));
        float hn = sqrtf(fmaxf(2.0f - 2.0f * maxDot, 1e-12f));
        float tl = hp - hn + 0.5f;
        if (tl < 0.0f) tl = 0.0f;
        sum += tl;
        cnt++;
    }
#pragma unroll
    for (int s = 16; s > 0; s >>= 1) {
        sum += __shfl_down_sync(0xffffffffu, sum, s);
        cnt += __shfl_down_sync(0xffffffffu, cnt, s);
    }
    if (lane == 0) { sSum[wid] = sum; sCnt[wid] = cnt; }
    __syncthreads();
    if (wid == 0) {
        float s2 = sSum[lane];
        unsigned c2 = sCnt[lane];
#pragma unroll
        for (int s = 16; s > 0; s >>= 1) {
            s2 += __shfl_down_sync(0xffffffffu, s2, s);
            c2 += __shfl_down_sync(0xffffffffu, c2, s);
        }
        if (lane == 0) out[0] = s2 / (float)(c2 > 0u ? c2 : 1u);
    }
    for (int i = tid; i < out_size; i += 1024)
        if (i > 0) out[i] = 0.0f;
}

// ---------------- launch ----------------
extern "C" void kernel_launch(void* const* d_in, const int* in_sizes, int n_in,
                              void* d_out, int out_size) {
    const float* emb = (const float*)d_in[0];
    const float* tg = (const float*)d_in[1];
    const float* au = (const float*)d_in[2];
    float* out = (float*)d_out;

    prepK<<<130, 1024>>>(emb, au, tg);
    selectK<<<2, 1024>>>();
    gemmMaskK<<<528, 256>>>(tg);
    finalK<<<1, 1024>>>(out, out_size);
}